// round 6
// baseline (speedup 1.0000x reference)
#include <cuda_runtime.h>
#include <cstddef>

#define NN 16384
#define CC 10000
#define DD 128
#define LR 0.5f

#define NVEC (CC / 4)   // 2500 float4 per label row

// Scratch (no cudaMalloc allowed). Zero-initialized at module load; the
// finalize kernel re-zeroes after each use so every graph replay starts clean.
__device__ float g_sum[CC * DD];  // per-class sum of preds
__device__ float g_cnt[CC];      // per-class sample count

// ---------------------------------------------------------------------------
// Kernel 1: one block per sample. Barrier-free early-exit scan:
// thread t reads float4 indices t, t+256, t+512, ... (each iteration the
// block consumes ~4KB). A volatile shared flag is polled BEFORE each load, so
// byte consumption stops within ~1 iteration of the 1.0 being found.
// E[bytes/row] ~ (40KB + 4KB)/2 ~ 22KB  (vs 24KB with 8KB barrier chunks),
// with zero per-chunk barrier cost. Then accumulate preds into the class
// accumulator via red-atomics.
// ---------------------------------------------------------------------------
__global__ void __launch_bounds__(256, 8) cl_scan_accum_kernel(
    const float* __restrict__ labels,   // [N, C]
    const float* __restrict__ preds)    // [N, D]
{
    __shared__ volatile int s_cls;
    const int n = blockIdx.x;
    const int t = threadIdx.x;

    if (t == 0) s_cls = -1;
    __syncthreads();

    const float4* __restrict__ row =
        reinterpret_cast<const float4*>(labels + (size_t)n * CC);

    int cls = -1;
    #pragma unroll 1
    for (int i = t; i < NVEC; i += 256) {
        if (s_cls >= 0) break;               // poll before spending bytes
        float4 v = __ldcs(&row[i]);          // streaming: don't pollute L2
        if (v.x != 0.0f)      cls = 4 * i + 0;
        else if (v.y != 0.0f) cls = 4 * i + 1;
        else if (v.z != 0.0f) cls = 4 * i + 2;
        else if (v.w != 0.0f) cls = 4 * i + 3;
        if (cls >= 0) { s_cls = cls; break; } // exactly one writer, once
    }
    __syncthreads();                          // drains finder's STS
    cls = s_cls;

    if (t < DD) {
        // Return value unused -> compiles to RED (no round trip).
        atomicAdd(&g_sum[(size_t)cls * DD + t], __ldg(&preds[(size_t)n * DD + t]));
    }
    if (t == 0) {
        atomicAdd(&g_cnt[cls], 1.0f);
    }
}

// ---------------------------------------------------------------------------
// Kernel 2: finalize (float4-vectorized) + re-zero scratch for next replay.
//   grad[c] = (cnt[c]*center[c] - sum_preds[c]) / (cnt[c] + 1)
//   out[c]  = center[c] - LR * grad[c]
// One thread = one float4. 32 float4 per class; a 256-thread block covers
// exactly 8 whole classes, so g_cnt[c] is private to the block:
// read before the barrier, zero after it.
// ---------------------------------------------------------------------------
__global__ void __launch_bounds__(256) cl_finalize_kernel(
    const float* __restrict__ center,   // [C, D]
    float* __restrict__ out)            // [C, D]
{
    const int i4 = blockIdx.x * 256 + threadIdx.x;   // float4 index
    const int c  = i4 >> 5;                          // 32 float4 per class

    const float cnt = g_cnt[c];
    const float inv = 1.0f / (cnt + 1.0f);
    const float a   = 1.0f - LR * cnt * inv;         // coeff on center
    const float b   = LR * inv;                      // coeff on sum

    float4 s   = reinterpret_cast<float4*>(g_sum)[i4];
    float4 ctr = reinterpret_cast<const float4*>(center)[i4];

    float4 r;
    r.x = a * ctr.x + b * s.x;
    r.y = a * ctr.y + b * s.y;
    r.z = a * ctr.z + b * s.z;
    r.w = a * ctr.w + b * s.w;
    reinterpret_cast<float4*>(out)[i4] = r;

    reinterpret_cast<float4*>(g_sum)[i4] = make_float4(0.f, 0.f, 0.f, 0.f);
    __syncthreads();                     // all g_cnt reads in this block done
    if ((threadIdx.x & 31) == 0) {
        g_cnt[c] = 0.0f;                 // 8 distinct classes per block
    }
}

// ---------------------------------------------------------------------------
// Launch. Inputs per metadata: embeded_preds [N*D], labels [N*C],
// center [C*D]. Output: updated_center [C*D] float32.
// ---------------------------------------------------------------------------
extern "C" void kernel_launch(void* const* d_in, const int* in_sizes, int n_in,
                              void* d_out, int out_size) {
    const float* preds  = (const float*)d_in[0];
    const float* labels = (const float*)d_in[1];
    const float* center = (const float*)d_in[2];
    float* out = (float*)d_out;

    (void)in_sizes; (void)n_in; (void)out_size;

    cl_scan_accum_kernel<<<NN, 256>>>(labels, preds);
    cl_finalize_kernel<<<(CC * DD / 4) / 256, 256>>>(center, out);
}

// round 7
// speedup vs baseline: 1.2005x; 1.2005x over previous
#include <cuda_runtime.h>
#include <cstddef>

#define NN 16384
#define CC 10000
#define DD 128
#define LR 0.5f

#define NVEC   (CC / 4)   // 2500 float4 per label row
#define SCANT  64         // threads per scan block (2 warps)
#define CHUNKV (SCANT*2)  // float4 per chunk = 128 -> 2KB lockstep chunks

// Scratch (no cudaMalloc allowed). Zero-initialized at module load; the
// finalize kernel re-zeroes after each use so every graph replay starts clean.
__device__ float g_sum[CC * DD];  // per-class sum of preds
__device__ float g_cnt[CC];      // per-class sample count

// ---------------------------------------------------------------------------
// Kernel 1: one 64-thread block per sample. Lockstep early-exit scan in 2KB
// chunks (2 float4 in flight per thread, barrier per chunk so no warp
// overshoots). E[bytes/row] ~ (40KB + 2KB)/2 = 21KB. Then accumulate the
// sample's 128-dim pred vector into the class accumulator via red-atomics
// (each thread covers 2 dims).
// ---------------------------------------------------------------------------
__global__ void __launch_bounds__(SCANT) cl_scan_accum_kernel(
    const float* __restrict__ labels,   // [N, C]
    const float* __restrict__ preds)    // [N, D]
{
    __shared__ int s_cls;
    const int n = blockIdx.x;
    const int t = threadIdx.x;

    if (t == 0) s_cls = -1;
    __syncthreads();

    const float4* __restrict__ row =
        reinterpret_cast<const float4*>(labels + (size_t)n * CC);

    int cls = -1;
    #pragma unroll 1
    for (int base = 0; base < NVEC; base += CHUNKV) {
        const int i0 = base + t;
        const int i1 = base + t + SCANT;
        int found = -1;

        // Two independent loads in flight per thread (MLP=2).
        float4 v0, v1;
        const bool p0 = (i0 < NVEC);
        const bool p1 = (i1 < NVEC);
        if (p0) v0 = __ldg(&row[i0]);
        if (p1) v1 = __ldg(&row[i1]);

        if (p0) {
            if (v0.x != 0.0f)      found = 4 * i0 + 0;
            else if (v0.y != 0.0f) found = 4 * i0 + 1;
            else if (v0.z != 0.0f) found = 4 * i0 + 2;
            else if (v0.w != 0.0f) found = 4 * i0 + 3;
        }
        if (found < 0 && p1) {
            if (v1.x != 0.0f)      found = 4 * i1 + 0;
            else if (v1.y != 0.0f) found = 4 * i1 + 1;
            else if (v1.z != 0.0f) found = 4 * i1 + 2;
            else if (v1.w != 0.0f) found = 4 * i1 + 3;
        }

        if (found >= 0) s_cls = found;   // at most one thread writes, once
        __syncthreads();                 // write visible, lockstep advance
        cls = s_cls;                     // uniform read
        __syncthreads();                 // reads done before later write
        if (cls >= 0) break;             // uniform branch
    }

    const int c = cls;
    // Accumulate preds[n,:] into g_sum[c,:]; 64 threads x 2 dims.
    const float* __restrict__ pr = preds + (size_t)n * DD;
    atomicAdd(&g_sum[(size_t)c * DD + t],         __ldg(&pr[t]));
    atomicAdd(&g_sum[(size_t)c * DD + t + SCANT], __ldg(&pr[t + SCANT]));
    if (t == 0) {
        atomicAdd(&g_cnt[c], 1.0f);
    }
}

// ---------------------------------------------------------------------------
// Kernel 2: finalize (float4 + 2x ILP) + re-zero scratch for next replay.
//   out[c] = (1 - LR*cnt/(cnt+1)) * center[c] + (LR/(cnt+1)) * sum[c]
// Thread handles float4 indices {2*i, 2*i+1}; since each class spans 32
// float4 (even) and the pair differs by 1, both lie in the same class.
// A 256-thread block covers 512 float4 = 16 whole classes, so g_cnt is
// block-private: read before the barrier, zero after it.
// ---------------------------------------------------------------------------
__global__ void __launch_bounds__(256) cl_finalize_kernel(
    const float* __restrict__ center,   // [C, D]
    float* __restrict__ out)            // [C, D]
{
    const int i  = blockIdx.x * 256 + threadIdx.x;
    const int i4 = 2 * i;                       // first float4 index
    const int c  = i4 >> 5;                     // 32 float4 per class

    const float4* __restrict__ gs = reinterpret_cast<const float4*>(g_sum);
    const float4* __restrict__ gc = reinterpret_cast<const float4*>(center);

    const float cnt = g_cnt[c];
    float4 s0 = gs[i4],     s1 = gs[i4 + 1];
    float4 c0 = gc[i4],     c1 = gc[i4 + 1];

    const float inv = 1.0f / (cnt + 1.0f);
    const float a   = 1.0f - LR * cnt * inv;    // coeff on center
    const float b   = LR * inv;                 // coeff on sum

    float4 r0, r1;
    r0.x = a * c0.x + b * s0.x;  r0.y = a * c0.y + b * s0.y;
    r0.z = a * c0.z + b * s0.z;  r0.w = a * c0.w + b * s0.w;
    r1.x = a * c1.x + b * s1.x;  r1.y = a * c1.y + b * s1.y;
    r1.z = a * c1.z + b * s1.z;  r1.w = a * c1.w + b * s1.w;

    float4* __restrict__ po = reinterpret_cast<float4*>(out);
    po[i4]     = r0;
    po[i4 + 1] = r1;

    float4* gsw = reinterpret_cast<float4*>(g_sum);
    const float4 z = make_float4(0.f, 0.f, 0.f, 0.f);
    gsw[i4] = z;
    gsw[i4 + 1] = z;

    __syncthreads();                    // all g_cnt reads in this block done
    if ((i & 15) == 0) {                // first pair of each class
        g_cnt[c] = 0.0f;
    }
}

// ---------------------------------------------------------------------------
// Launch. Inputs per metadata: embeded_preds [N*D], labels [N*C],
// center [C*D]. Output: updated_center [C*D] float32.
// ---------------------------------------------------------------------------
extern "C" void kernel_launch(void* const* d_in, const int* in_sizes, int n_in,
                              void* d_out, int out_size) {
    const float* preds  = (const float*)d_in[0];
    const float* labels = (const float*)d_in[1];
    const float* center = (const float*)d_in[2];
    float* out = (float*)d_out;

    (void)in_sizes; (void)n_in; (void)out_size;

    cl_scan_accum_kernel<<<NN, SCANT>>>(labels, preds);
    cl_finalize_kernel<<<(CC * DD / 8) / 256, 256>>>(center, out);
}